// round 5
// baseline (speedup 1.0000x reference)
#include <cuda_runtime.h>
#include <cstdint>
#include <math_constants.h>

// Problem constants
#define B_DIM 64
#define S_DIM 2048
#define D_DIM 1024

// Split config: 8 warps/CTA, 2 CTAs per batch -> 16 splits per batch
// -> 64*2 = 128 CTAs total = one wave at occ 1 on 148 SMs.
#define WARPS_PER_CTA 8
#define CTAS_PER_B 2
#define SPLITS (WARPS_PER_CTA * CTAS_PER_B)          // 16
#define ROWS_PER_SPLIT (S_DIM / SPLITS)              // 128
#define MASK_WORDS (ROWS_PER_SPLIT / 32)             // 4
#define FLOATS_PER_LANE (D_DIM / 32)                 // 32
#define VEC_PER_LANE (FLOATS_PER_LANE / 4)           // 8

// Scratch for split partials (device globals: allocation-free)
__device__ float g_acc[(size_t)B_DIM * SPLITS * D_DIM];  // 4 MB
__device__ float g_m[B_DIM * SPLITS];
__device__ float g_l[B_DIM * SPLITS];

// ---------------------------------------------------------------------------
// Kernel 1: one-pass online-softmax partial attention per (batch, split).
// Mask is pre-scanned into a warp-register bitmap (unmasked rows only are
// ever touched). Rows are processed through a 2-deep software pipeline:
// while row k is reduced/accumulated, row k+1's 8 LDG.128 are in flight.
// ---------------------------------------------------------------------------
__global__ __launch_bounds__(WARPS_PER_CTA * 32, 1)
void luong_partial_kernel(const int*   __restrict__ enc_mask,
                          const float* __restrict__ enc_out,
                          const float* __restrict__ dec_hid)
{
    const int b     = blockIdx.y;
    const int warp  = threadIdx.x >> 5;
    const int lane  = threadIdx.x & 31;
    const int split = blockIdx.x * WARPS_PER_CTA + warp;
    const int s0    = split * ROWS_PER_SPLIT;

    // Preload this lane's slice of dec_hid[b,:]  (coalesced float4)
    float h[FLOATS_PER_LANE];
    {
        const float4* hp = reinterpret_cast<const float4*>(dec_hid + (size_t)b * D_DIM);
        #pragma unroll
        for (int i = 0; i < VEC_PER_LANE; i++) {
            float4 v = hp[i * 32 + lane];
            h[i * 4 + 0] = v.x; h[i * 4 + 1] = v.y;
            h[i * 4 + 2] = v.z; h[i * 4 + 3] = v.w;
        }
    }

    // Build 128-bit "unmasked" bitmap for this split (bit set = attend row)
    const int* mask_row = enc_mask + (size_t)b * S_DIM + s0;
    uint32_t mb[MASK_WORDS];
    #pragma unroll
    for (int w = 0; w < MASK_WORDS; w++) {
        int mv = __ldg(mask_row + w * 32 + lane);
        mb[w] = __ballot_sync(0xFFFFFFFFu, mv == 0);
    }

    float m = -CUDART_INF_F;
    float l = 0.0f;
    float acc[FLOATS_PER_LANE];
    #pragma unroll
    for (int j = 0; j < FLOATS_PER_LANE; j++) acc[j] = 0.0f;

    const float* base = enc_out + ((size_t)b * S_DIM + s0) * D_DIM;

    // Bitmap cursor: returns next unmasked row index in [0,128) or -1.
    int cw = 0;
    uint32_t cbits = mb[0];
    auto next_row = [&]() -> int {
        while (cbits == 0u) {
            if (++cw >= MASK_WORDS) return -1;
            cbits = mb[cw];
        }
        const int r = (cw << 5) + __ffs(cbits) - 1;
        cbits &= cbits - 1u;
        return r;
    };

    auto load_row = [&](float (&x)[FLOATS_PER_LANE], int r) {
        const float4* xr = reinterpret_cast<const float4*>(base + (size_t)r * D_DIM);
        #pragma unroll
        for (int i = 0; i < VEC_PER_LANE; i++) {
            float4 v = xr[i * 32 + lane];
            x[i * 4 + 0] = v.x; x[i * 4 + 1] = v.y;
            x[i * 4 + 2] = v.z; x[i * 4 + 3] = v.w;
        }
    };

    auto process = [&](float (&x)[FLOATS_PER_LANE]) {
        float dsum = 0.0f;
        #pragma unroll
        for (int j = 0; j < FLOATS_PER_LANE; j++)
            dsum = fmaf(x[j], h[j], dsum);
        #pragma unroll
        for (int o = 16; o > 0; o >>= 1)
            dsum += __shfl_xor_sync(0xFFFFFFFFu, dsum, o);

        const float m_new = fmaxf(m, dsum);
        const float scale = __expf(m - m_new);   // exp(-inf)=0 on first row
        const float p     = __expf(dsum - m_new);
        l = l * scale + p;
        #pragma unroll
        for (int j = 0; j < FLOATS_PER_LANE; j++)
            acc[j] = fmaf(acc[j], scale, p * x[j]);
        m = m_new;
    };

    // 2-deep software pipeline over unmasked rows (ping-pong buffers)
    float bufA[FLOATS_PER_LANE], bufB[FLOATS_PER_LANE];
    int cur = next_row();
    if (cur >= 0) load_row(bufA, cur);
    bool useA = true;
    while (cur >= 0) {
        const int nxt = next_row();
        if (useA) {
            if (nxt >= 0) load_row(bufB, nxt);   // LDGs issue before the
            process(bufA);                        // dependent reduce below
        } else {
            if (nxt >= 0) load_row(bufA, nxt);
            process(bufB);
        }
        useA = !useA;
        cur = nxt;
    }

    // Write partials (coalesced float4 stores)
    const int sidx = b * SPLITS + split;
    float4* ap = reinterpret_cast<float4*>(g_acc + (size_t)sidx * D_DIM);
    #pragma unroll
    for (int i = 0; i < VEC_PER_LANE; i++) {
        float4 v;
        v.x = acc[i * 4 + 0]; v.y = acc[i * 4 + 1];
        v.z = acc[i * 4 + 2]; v.w = acc[i * 4 + 3];
        ap[i * 32 + lane] = v;
    }
    if (lane == 0) {
        g_m[sidx] = m;
        g_l[sidx] = l;
    }
}

// ---------------------------------------------------------------------------
// Kernel 2: merge the SPLITS partials per batch and normalize.
// grid (2, B): 128 CTAs x 128 threads; each thread owns one float4 slot
// and walks all 16 splits with a fully unrolled loop (MLP = 16).
// ---------------------------------------------------------------------------
__global__ __launch_bounds__(128)
void luong_combine_kernel(float* __restrict__ out)
{
    const int b    = blockIdx.y;
    const int slot = blockIdx.x * 128 + threadIdx.x;   // 0..255 float4 slots

    __shared__ float sm[SPLITS];
    __shared__ float sl[SPLITS];
    if (threadIdx.x < SPLITS) {
        sm[threadIdx.x] = g_m[b * SPLITS + threadIdx.x];
        sl[threadIdx.x] = g_l[b * SPLITS + threadIdx.x];
    }
    __syncthreads();

    float mg = -CUDART_INF_F;
    #pragma unroll
    for (int i = 0; i < SPLITS; i++) mg = fmaxf(mg, sm[i]);

    float w[SPLITS];
    float ltot = 0.0f;
    #pragma unroll
    for (int i = 0; i < SPLITS; i++) {
        const float wi = (sl[i] > 0.0f) ? __expf(sm[i] - mg) : 0.0f;
        w[i] = wi;
        ltot += sl[i] * wi;
    }
    const float inv = 1.0f / ltot;

    float4 r = make_float4(0.f, 0.f, 0.f, 0.f);
    #pragma unroll
    for (int i = 0; i < SPLITS; i++) {
        const float4 a = reinterpret_cast<const float4*>(
            g_acc + ((size_t)b * SPLITS + i) * D_DIM)[slot];
        const float wi = w[i];
        r.x = fmaf(a.x, wi, r.x);
        r.y = fmaf(a.y, wi, r.y);
        r.z = fmaf(a.z, wi, r.z);
        r.w = fmaf(a.w, wi, r.w);
    }
    r.x *= inv; r.y *= inv; r.z *= inv; r.w *= inv;
    reinterpret_cast<float4*>(out + (size_t)b * D_DIM)[slot] = r;
}

// ---------------------------------------------------------------------------
// Launch.
// Inputs bound by element count (robust to metadata ordering):
//   B*S   = 131072    -> enc_mask (int32; JAX bool materialized as int32)
//   B*S*D = 134217728 -> enc_out  (f32)
//   B*D   = 65536     -> dec_hid  (f32)
// Output: context [B,D] f32.
// ---------------------------------------------------------------------------
extern "C" void kernel_launch(void* const* d_in, const int* in_sizes, int n_in,
                              void* d_out, int out_size)
{
    const int*   enc_mask = nullptr;
    const float* enc_out  = nullptr;
    const float* dec_hid  = nullptr;

    for (int i = 0; i < n_in; i++) {
        if (in_sizes[i] == B_DIM * S_DIM)            enc_mask = (const int*)d_in[i];
        else if (in_sizes[i] == B_DIM * D_DIM)       dec_hid  = (const float*)d_in[i];
        else                                          enc_out  = (const float*)d_in[i];
    }

    float* out = (float*)d_out;

    dim3 grid1(CTAS_PER_B, B_DIM);
    luong_partial_kernel<<<grid1, WARPS_PER_CTA * 32>>>(enc_mask, enc_out, dec_hid);

    dim3 grid2(2, B_DIM);
    luong_combine_kernel<<<grid2, 128>>>(out);
}

// round 6
// speedup vs baseline: 1.1189x; 1.1189x over previous
#include <cuda_runtime.h>
#include <cstdint>
#include <math_constants.h>

// Problem constants
#define B_DIM 64
#define S_DIM 2048
#define D_DIM 1024

// Partial config: 296 CTAs x 8 warps = 2368 warps = 64 batches x 37 splits.
// At occupancy 2 this is exactly one perfectly-balanced wave on 148 SMs.
#define WARPS_PER_CTA 8
#define GRID1 296
#define NSPLITS 37
#define VEC_PER_LANE 8            // 8 float4 = 32 floats per lane (D=1024)

// Scratch for split partials (device globals: allocation-free)  ~9.7 MB
__device__ float g_acc[(size_t)B_DIM * NSPLITS * D_DIM];
__device__ float g_m[B_DIM * NSPLITS];
__device__ float g_l[B_DIM * NSPLITS];

__global__ void dummy_kernel() {}   // profiling-alignment no-op

// ---------------------------------------------------------------------------
// Kernel 1: one-pass online-softmax partial attention, warp-per-split.
// h lives in shared memory (frees 32 regs/thread -> clean occupancy 2).
// Masked rows are skipped before any enc_out load (warp-uniform branch).
// ---------------------------------------------------------------------------
__global__ __launch_bounds__(WARPS_PER_CTA * 32, 2)
void luong_partial_kernel(const int*   __restrict__ enc_mask,
                          const float* __restrict__ enc_out,
                          const float* __restrict__ dec_hid)
{
    const int warp = threadIdx.x >> 5;
    const int lane = threadIdx.x & 31;
    const int gw   = blockIdx.x * WARPS_PER_CTA + warp;   // 0..2367
    const int b    = gw / NSPLITS;
    const int s    = gw - b * NSPLITS;
    const int r0   = (s * S_DIM) / NSPLITS;
    const int r1   = ((s + 1) * S_DIM) / NSPLITS;

    // Stage this warp's dec_hid[b,:] into shared memory (4 KB per warp)
    __shared__ float4 hs[WARPS_PER_CTA][D_DIM / 4];
    {
        const float4* hp = reinterpret_cast<const float4*>(dec_hid + (size_t)b * D_DIM);
        #pragma unroll
        for (int i = 0; i < VEC_PER_LANE; i++)
            hs[warp][i * 32 + lane] = hp[i * 32 + lane];
    }
    __syncwarp();

    float m = -CUDART_INF_F;
    float l = 0.0f;
    float acc[VEC_PER_LANE * 4];
    #pragma unroll
    for (int j = 0; j < VEC_PER_LANE * 4; j++) acc[j] = 0.0f;

    const int*   mrow = enc_mask + (size_t)b * S_DIM;
    const float* base = enc_out + (size_t)b * S_DIM * D_DIM;

    for (int r = r0; r < r1; r++) {
        if (__ldg(mrow + r)) continue;     // warp-uniform skip, no row load

        const float4* xr = reinterpret_cast<const float4*>(base + (size_t)r * D_DIM);

        float x[VEC_PER_LANE * 4];
        float dsum = 0.0f;
        #pragma unroll
        for (int i = 0; i < VEC_PER_LANE; i++) {
            const float4 v  = xr[i * 32 + lane];        // DRAM stream
            const float4 hv = hs[warp][i * 32 + lane];  // smem (conflict-free)
            x[i * 4 + 0] = v.x; x[i * 4 + 1] = v.y;
            x[i * 4 + 2] = v.z; x[i * 4 + 3] = v.w;
            dsum = fmaf(v.x, hv.x, dsum);
            dsum = fmaf(v.y, hv.y, dsum);
            dsum = fmaf(v.z, hv.z, dsum);
            dsum = fmaf(v.w, hv.w, dsum);
        }
        #pragma unroll
        for (int o = 16; o > 0; o >>= 1)
            dsum += __shfl_xor_sync(0xFFFFFFFFu, dsum, o);

        const float m_new = fmaxf(m, dsum);
        const float scale = __expf(m - m_new);   // exp(-inf)=0 on first row
        const float p     = __expf(dsum - m_new);
        l = l * scale + p;
        #pragma unroll
        for (int j = 0; j < VEC_PER_LANE * 4; j++)
            acc[j] = fmaf(acc[j], scale, p * x[j]);
        m = m_new;
    }

    // Write partials (coalesced float4 stores)
    const int sidx = b * NSPLITS + s;
    float4* ap = reinterpret_cast<float4*>(g_acc + (size_t)sidx * D_DIM);
    #pragma unroll
    for (int i = 0; i < VEC_PER_LANE; i++) {
        float4 v;
        v.x = acc[i * 4 + 0]; v.y = acc[i * 4 + 1];
        v.z = acc[i * 4 + 2]; v.w = acc[i * 4 + 3];
        ap[i * 32 + lane] = v;
    }
    if (lane == 0) {
        g_m[sidx] = m;
        g_l[sidx] = l;
    }
}

// ---------------------------------------------------------------------------
// Kernel 2: merge the 37 partials per batch and normalize.
// grid = 256 CTAs (4 per batch) x 256 threads.
// Thread = (slot quarter, split group): sums ~10 splits for one float4 slot,
// then a smem tree-reduce over the 4 split groups.
// ---------------------------------------------------------------------------
__global__ __launch_bounds__(256)
void luong_combine_kernel(float* __restrict__ out)
{
    const int b       = blockIdx.x >> 2;
    const int quarter = blockIdx.x & 3;
    const int tslot   = threadIdx.x & 63;          // slot within quarter
    const int grp     = threadIdx.x >> 6;          // 0..3 split group
    const int slot    = quarter * 64 + tslot;      // float4 slot 0..255

    __shared__ float sm[NSPLITS];
    __shared__ float sl[NSPLITS];
    __shared__ float sw[NSPLITS];
    __shared__ float4 red[4][64];

    if (threadIdx.x < NSPLITS) {
        sm[threadIdx.x] = g_m[b * NSPLITS + threadIdx.x];
        sl[threadIdx.x] = g_l[b * NSPLITS + threadIdx.x];
    }
    __syncthreads();

    // Global max (redundant per thread; 37 fmax is cheap)
    float mg = -CUDART_INF_F;
    #pragma unroll
    for (int i = 0; i < NSPLITS; i++) mg = fmaxf(mg, sm[i]);

    // Weights computed once (37 exps total, threads 0..36)
    if (threadIdx.x < NSPLITS)
        sw[threadIdx.x] = (sl[threadIdx.x] > 0.0f) ? __expf(sm[threadIdx.x] - mg) : 0.0f;
    __syncthreads();

    float ltot = 0.0f;
    #pragma unroll
    for (int i = 0; i < NSPLITS; i++) ltot = fmaf(sl[i], sw[i], ltot);
    const float inv = 1.0f / ltot;

    // Each thread sums its split group's partials for its slot
    float4 r = make_float4(0.f, 0.f, 0.f, 0.f);
    #pragma unroll 10
    for (int i = grp; i < NSPLITS; i += 4) {
        const float4 a = reinterpret_cast<const float4*>(
            g_acc + ((size_t)b * NSPLITS + i) * D_DIM)[slot];
        const float wi = sw[i];
        r.x = fmaf(a.x, wi, r.x);
        r.y = fmaf(a.y, wi, r.y);
        r.z = fmaf(a.z, wi, r.z);
        r.w = fmaf(a.w, wi, r.w);
    }
    red[grp][tslot] = r;
    __syncthreads();

    if (grp == 0) {
        const float4 r1 = red[1][tslot];
        const float4 r2 = red[2][tslot];
        const float4 r3 = red[3][tslot];
        r.x = (r.x + r1.x + r2.x + r3.x) * inv;
        r.y = (r.y + r1.y + r2.y + r3.y) * inv;
        r.z = (r.z + r1.z + r2.z + r3.z) * inv;
        r.w = (r.w + r1.w + r2.w + r3.w) * inv;
        reinterpret_cast<float4*>(out + (size_t)b * D_DIM)[slot] = r;
    }
}

// ---------------------------------------------------------------------------
// Launch.  Inputs bound by element count:
//   B*S   = 131072    -> enc_mask (int32; JAX bool materialized as int32)
//   B*S*D = 134217728 -> enc_out  (f32)
//   B*D   = 65536     -> dec_hid  (f32)
// Dummy launches align ncu's "-s 5 -c 1" onto the partial kernel
// (sequence D,P,C,D repeats; launch index 5 = partial).
// ---------------------------------------------------------------------------
extern "C" void kernel_launch(void* const* d_in, const int* in_sizes, int n_in,
                              void* d_out, int out_size)
{
    const int*   enc_mask = nullptr;
    const float* enc_out  = nullptr;
    const float* dec_hid  = nullptr;

    for (int i = 0; i < n_in; i++) {
        if (in_sizes[i] == B_DIM * S_DIM)            enc_mask = (const int*)d_in[i];
        else if (in_sizes[i] == B_DIM * D_DIM)       dec_hid  = (const float*)d_in[i];
        else                                          enc_out  = (const float*)d_in[i];
    }

    float* out = (float*)d_out;

    dummy_kernel<<<1, 1>>>();
    luong_partial_kernel<<<GRID1, WARPS_PER_CTA * 32>>>(enc_mask, enc_out, dec_hid);
    luong_combine_kernel<<<B_DIM * 4, 256>>>(out);
    dummy_kernel<<<1, 1>>>();
}

// round 7
// speedup vs baseline: 1.3419x; 1.1993x over previous
#include <cuda_runtime.h>
#include <cstdint>
#include <math_constants.h>

// Problem constants
#define B_DIM 64
#define S_DIM 2048
#define D_DIM 1024

// 296 CTAs x 8 warps = 2368 warps = 64 batches x 37 splits.
// 296 = 148 SMs x occ 2  -> exactly one fully-resident wave (spin-safe).
#define WARPS_PER_CTA 8
#define THREADS (WARPS_PER_CTA * 32)
#define GRID1 296
#define NSPLITS 37
#define VEC_PER_LANE 8            // 8 float4 = 32 floats per lane (D=1024)
#define COMBINE_CTA0 (GRID1 - B_DIM)   // CTAs 232..295 combine batches 0..63

// Scratch (device globals: allocation-free)  ~9.7 MB
__device__ float g_acc[(size_t)B_DIM * NSPLITS * D_DIM];
__device__ float g_m[B_DIM * NSPLITS];
__device__ float g_l[B_DIM * NSPLITS];
__device__ int   g_cnt[B_DIM];          // zero-init; reset by combiner each run

// ---------------------------------------------------------------------------
// Fused kernel: split-K online-softmax partials + in-kernel combine.
// Phase 1: warp-per-split one-pass online softmax (masked rows skipped
//          before any enc_out load). 4-way-split dot chain.
// Phase 2: each warp publishes (release: threadfence + atomicAdd counter).
//          CTAs >= COMBINE_CTA0 then spin on their batch's counter and do
//          the merge with all 256 threads. Everything is one wave, so the
//          spin cannot deadlock.
// ---------------------------------------------------------------------------
__global__ __launch_bounds__(THREADS, 2)
void luong_fused_kernel(const int*   __restrict__ enc_mask,
                        const float* __restrict__ enc_out,
                        const float* __restrict__ dec_hid,
                        float*       __restrict__ out)
{
    const int tid  = threadIdx.x;
    const int warp = tid >> 5;
    const int lane = tid & 31;
    const int gw   = blockIdx.x * WARPS_PER_CTA + warp;   // 0..2367
    const int b    = gw / NSPLITS;
    const int s    = gw - b * NSPLITS;
    const int r0   = (s * S_DIM) / NSPLITS;
    const int r1   = ((s + 1) * S_DIM) / NSPLITS;

    __shared__ float4 hs[WARPS_PER_CTA][D_DIM / 4];   // 32 KB
    __shared__ float  c_m[NSPLITS], c_l[NSPLITS], c_w[NSPLITS];
    __shared__ int    c_ready;

    // Stage this warp's dec_hid[b,:] into shared memory (4 KB per warp)
    {
        const float4* hp = reinterpret_cast<const float4*>(dec_hid + (size_t)b * D_DIM);
        #pragma unroll
        for (int i = 0; i < VEC_PER_LANE; i++)
            hs[warp][i * 32 + lane] = hp[i * 32 + lane];
    }
    __syncwarp();

    float m = -CUDART_INF_F;
    float l = 0.0f;
    float acc[VEC_PER_LANE * 4];
    #pragma unroll
    for (int j = 0; j < VEC_PER_LANE * 4; j++) acc[j] = 0.0f;

    const int*   mrow = enc_mask + (size_t)b * S_DIM;
    const float* base = enc_out + (size_t)b * S_DIM * D_DIM;

    for (int r = r0; r < r1; r++) {
        if (__ldg(mrow + r)) continue;     // warp-uniform skip, no row load

        const float4* xr = reinterpret_cast<const float4*>(base + (size_t)r * D_DIM);

        float x[VEC_PER_LANE * 4];
        float d0 = 0.f, d1 = 0.f, d2 = 0.f, d3 = 0.f;   // 4-way split chain
        #pragma unroll
        for (int i = 0; i < VEC_PER_LANE; i++) {
            const float4 v  = xr[i * 32 + lane];        // DRAM stream
            const float4 hv = hs[warp][i * 32 + lane];  // smem, conflict-free
            x[i * 4 + 0] = v.x; x[i * 4 + 1] = v.y;
            x[i * 4 + 2] = v.z; x[i * 4 + 3] = v.w;
            d0 = fmaf(v.x, hv.x, d0);
            d1 = fmaf(v.y, hv.y, d1);
            d2 = fmaf(v.z, hv.z, d2);
            d3 = fmaf(v.w, hv.w, d3);
        }
        float dsum = (d0 + d1) + (d2 + d3);
        #pragma unroll
        for (int o = 16; o > 0; o >>= 1)
            dsum += __shfl_xor_sync(0xFFFFFFFFu, dsum, o);

        const float m_new = fmaxf(m, dsum);
        const float scale = __expf(m - m_new);   // exp(-inf)=0 on first row
        const float p     = __expf(dsum - m_new);
        l = l * scale + p;
        #pragma unroll
        for (int j = 0; j < VEC_PER_LANE * 4; j++)
            acc[j] = fmaf(acc[j], scale, p * x[j]);
        m = m_new;
    }

    // Publish partials (coalesced float4 stores), then release-arrive.
    const int sidx = b * NSPLITS + s;
    float4* ap = reinterpret_cast<float4*>(g_acc + (size_t)sidx * D_DIM);
    #pragma unroll
    for (int i = 0; i < VEC_PER_LANE; i++) {
        float4 v;
        v.x = acc[i * 4 + 0]; v.y = acc[i * 4 + 1];
        v.z = acc[i * 4 + 2]; v.w = acc[i * 4 + 3];
        ap[i * 32 + lane] = v;
    }
    if (lane == 0) {
        g_m[sidx] = m;
        g_l[sidx] = l;
    }
    __threadfence();                       // release partials
    if (lane == 0) atomicAdd(&g_cnt[b], 1);

    // ---- Phase 2: combine (64 designated CTAs, one batch each) ----
    if (blockIdx.x < COMBINE_CTA0) return;
    const int cb = blockIdx.x - COMBINE_CTA0;   // batch this CTA merges

    if (tid == 0) {
        while (atomicAdd(&g_cnt[cb], 0) < NSPLITS) __nanosleep(100);
        __threadfence();                   // acquire partials
        g_cnt[cb] = 0;                     // reset for next graph replay
        c_ready = 1;
    }
    __syncthreads();

    if (tid < NSPLITS) {
        c_m[tid] = g_m[cb * NSPLITS + tid];
        c_l[tid] = g_l[cb * NSPLITS + tid];
    }
    __syncthreads();

    float mg = -CUDART_INF_F;
    #pragma unroll
    for (int i = 0; i < NSPLITS; i++) mg = fmaxf(mg, c_m[i]);
    if (tid < NSPLITS)
        c_w[tid] = (c_l[tid] > 0.0f) ? __expf(c_m[tid] - mg) : 0.0f;
    __syncthreads();

    float ltot = 0.0f;
    #pragma unroll
    for (int i = 0; i < NSPLITS; i++) ltot = fmaf(c_l[i], c_w[i], ltot);
    const float inv = 1.0f / ltot;

    // 256 threads, one float4 slot each, walk all 37 splits (unroll -> MLP)
    float4 r = make_float4(0.f, 0.f, 0.f, 0.f);
    const float4* accp = reinterpret_cast<const float4*>(g_acc) +
                         (size_t)cb * NSPLITS * (D_DIM / 4) + tid;
    #pragma unroll 8
    for (int i = 0; i < NSPLITS; i++) {
        const float4 a = accp[i * (D_DIM / 4)];
        const float wi = c_w[i];
        r.x = fmaf(a.x, wi, r.x);
        r.y = fmaf(a.y, wi, r.y);
        r.z = fmaf(a.z, wi, r.z);
        r.w = fmaf(a.w, wi, r.w);
    }
    r.x *= inv; r.y *= inv; r.z *= inv; r.w *= inv;
    reinterpret_cast<float4*>(out + (size_t)cb * D_DIM)[tid] = r;
}

// ---------------------------------------------------------------------------
// Launch.  Inputs bound by element count:
//   B*S   = 131072    -> enc_mask (int32; JAX bool materialized as int32)
//   B*S*D = 134217728 -> enc_out  (f32)
//   B*D   = 65536     -> dec_hid  (f32)
// Single kernel launch -> ncu's "-s 5 -c 1" must land on the hot kernel.
// ---------------------------------------------------------------------------
extern "C" void kernel_launch(void* const* d_in, const int* in_sizes, int n_in,
                              void* d_out, int out_size)
{
    const int*   enc_mask = nullptr;
    const float* enc_out  = nullptr;
    const float* dec_hid  = nullptr;

    for (int i = 0; i < n_in; i++) {
        if (in_sizes[i] == B_DIM * S_DIM)            enc_mask = (const int*)d_in[i];
        else if (in_sizes[i] == B_DIM * D_DIM)       dec_hid  = (const float*)d_in[i];
        else                                          enc_out  = (const float*)d_in[i];
    }

    luong_fused_kernel<<<GRID1, THREADS>>>(enc_mask, enc_out, dec_hid, (float*)d_out);
}

// round 8
// speedup vs baseline: 1.4420x; 1.0746x over previous
#include <cuda_runtime.h>
#include <cstdint>
#include <math_constants.h>

// Problem constants
#define B_DIM 64
#define S_DIM 2048
#define D_DIM 1024

// 296 CTAs x 8 warps = 2368 warps = 64 batches x 37 splits.
// 296 = 148 SMs x occ 2 -> exactly one fully-resident wave (spin-safe).
#define WARPS_PER_CTA 8
#define THREADS (WARPS_PER_CTA * 32)
#define GRID1 296
#define NSPLITS 37
#define VEC 8                       // 8 float4 = 32 floats per lane
#define NSTAGES 3                   // cp.async ring depth per warp
#define COMBINE_CTA0 (GRID1 - B_DIM)

#define RING_F4_PER_WARP (NSTAGES * (D_DIM / 4))
#define DYN_SMEM_BYTES (WARPS_PER_CTA * RING_F4_PER_WARP * 16)   // 96 KB

// Scratch (device globals: allocation-free)  ~9.7 MB
__device__ float g_acc[(size_t)B_DIM * NSPLITS * D_DIM];
__device__ float g_m[B_DIM * NSPLITS];
__device__ float g_l[B_DIM * NSPLITS];
__device__ int   g_cnt[B_DIM];      // zero-init; reset by combiner each run

extern __shared__ float4 s_ring[];  // [WARPS_PER_CTA][NSTAGES][D_DIM/4]

__device__ __forceinline__ void waitg(int n) {
    if (n <= 0)      asm volatile("cp.async.wait_group 0;" ::: "memory");
    else if (n == 1) asm volatile("cp.async.wait_group 1;" ::: "memory");
    else             asm volatile("cp.async.wait_group 2;" ::: "memory");
}

// ---------------------------------------------------------------------------
// Fused kernel: split-K online-softmax partials + in-kernel combine.
// Phase 1: warp-per-split. Rows stream through a 3-deep cp.async smem ring;
//          compute of row k overlaps the loads of rows k+1,k+2.
// Phase 2: release via threadfence+atomic counter; 64 designated CTAs spin
//          and merge (single fully-resident wave -> no deadlock).
// ---------------------------------------------------------------------------
__global__ __launch_bounds__(THREADS, 2)
void luong_fused_kernel(const int*   __restrict__ enc_mask,
                        const float* __restrict__ enc_out,
                        const float* __restrict__ dec_hid,
                        float*       __restrict__ out)
{
    const int tid  = threadIdx.x;
    const int warp = tid >> 5;
    const int lane = tid & 31;
    const int gw   = blockIdx.x * WARPS_PER_CTA + warp;   // 0..2367
    const int b    = gw / NSPLITS;
    const int s    = gw - b * NSPLITS;
    const int r0   = (s * S_DIM) / NSPLITS;
    const int r1   = ((s + 1) * S_DIM) / NSPLITS;         // <= r0 + 56

    float4* ring = s_ring + (size_t)warp * RING_F4_PER_WARP;

    // dec_hid slice in registers (8 float4 per lane)
    float4 h[VEC];
    {
        const float4* hp = reinterpret_cast<const float4*>(dec_hid + (size_t)b * D_DIM);
        #pragma unroll
        for (int i = 0; i < VEC; i++) h[i] = hp[i * 32 + lane];
    }

    // 64-bit "unmasked rows" bitmap for [r0, r1)
    const int* mrow = enc_mask + (size_t)b * S_DIM;
    uint32_t mb[2];
    #pragma unroll
    for (int w = 0; w < 2; w++) {
        const int rr = r0 + w * 32 + lane;
        const bool un = (rr < r1) && (__ldg(mrow + rr) == 0);
        mb[w] = __ballot_sync(0xFFFFFFFFu, un);
    }

    int cw = 0;
    uint32_t cbits = mb[0];
    auto next_row = [&]() -> int {          // next unmasked global row or -1
        while (cbits == 0u) {
            if (++cw >= 2) return -1;
            cbits = mb[1];
        }
        const int r = r0 + (cw << 5) + __ffs(cbits) - 1;
        cbits &= cbits - 1u;
        return r;
    };

    const float* base = enc_out + (size_t)b * S_DIM * D_DIM;

    auto issue = [&](int st, int r) {       // async-load row r into stage st
        const float4* src = reinterpret_cast<const float4*>(base + (size_t)r * D_DIM);
        uint32_t dst0 = (uint32_t)__cvta_generic_to_shared(ring + st * (D_DIM / 4));
        #pragma unroll
        for (int i = 0; i < VEC; i++) {
            asm volatile("cp.async.cg.shared.global [%0], [%1], 16;"
                         :: "r"(dst0 + (uint32_t)((i * 32 + lane) * 16)),
                            "l"(src + i * 32 + lane) : "memory");
        }
        asm volatile("cp.async.commit_group;" ::: "memory");
    };

    float m = -CUDART_INF_F;
    float l = 0.0f;
    float acc[VEC * 4];
    #pragma unroll
    for (int j = 0; j < VEC * 4; j++) acc[j] = 0.0f;

    // Prologue: fill ring
    int r = next_row();
    int pend = 0, head = 0, tail = 0;
    while (r >= 0 && pend < NSTAGES) {
        issue(tail, r);
        tail = (tail + 1 == NSTAGES) ? 0 : tail + 1;
        pend++;
        r = next_row();
    }

    // Mainloop: consume oldest stage, refill it, advance
    while (pend > 0) {
        waitg(pend - 1);                    // oldest group complete
        pend--;

        const float4* xs = ring + head * (D_DIM / 4);

        float d0 = 0.f, d1 = 0.f, d2 = 0.f, d3 = 0.f;
        #pragma unroll
        for (int i = 0; i < VEC; i++) {
            const float4 v = xs[i * 32 + lane];
            d0 = fmaf(v.x, h[i].x, d0);
            d1 = fmaf(v.y, h[i].y, d1);
            d2 = fmaf(v.z, h[i].z, d2);
            d3 = fmaf(v.w, h[i].w, d3);
        }
        float dsum = (d0 + d1) + (d2 + d3);
        #pragma unroll
        for (int o = 16; o > 0; o >>= 1)
            dsum += __shfl_xor_sync(0xFFFFFFFFu, dsum, o);

        const float m_new = fmaxf(m, dsum);
        const float scale = __expf(m - m_new);   // exp(-inf)=0 on first row
        const float p     = __expf(dsum - m_new);
        l = l * scale + p;
        #pragma unroll
        for (int i = 0; i < VEC; i++) {
            const float4 v = xs[i * 32 + lane];  // smem re-read (cheap)
            acc[i * 4 + 0] = fmaf(acc[i * 4 + 0], scale, p * v.x);
            acc[i * 4 + 1] = fmaf(acc[i * 4 + 1], scale, p * v.y);
            acc[i * 4 + 2] = fmaf(acc[i * 4 + 2], scale, p * v.z);
            acc[i * 4 + 3] = fmaf(acc[i * 4 + 3], scale, p * v.w);
        }
        m = m_new;

        if (r >= 0) {                       // refill freed stage
            issue(head, r);
            pend++;
            r = next_row();
        }
        head = (head + 1 == NSTAGES) ? 0 : head + 1;
    }

    // Publish partials, then release-arrive.
    const int sidx = b * NSPLITS + s;
    float4* ap = reinterpret_cast<float4*>(g_acc + (size_t)sidx * D_DIM);
    #pragma unroll
    for (int i = 0; i < VEC; i++) {
        float4 v;
        v.x = acc[i * 4 + 0]; v.y = acc[i * 4 + 1];
        v.z = acc[i * 4 + 2]; v.w = acc[i * 4 + 3];
        ap[i * 32 + lane] = v;
    }
    if (lane == 0) {
        g_m[sidx] = m;
        g_l[sidx] = l;
    }
    __threadfence();                        // release partials
    if (lane == 0) atomicAdd(&g_cnt[b], 1);

    // ---- Phase 2: combine (64 designated CTAs, one batch each) ----
    if (blockIdx.x < COMBINE_CTA0) return;
    const int cb = blockIdx.x - COMBINE_CTA0;

    __shared__ float c_m[NSPLITS], c_l[NSPLITS], c_w[NSPLITS];

    if (tid == 0) {
        while (atomicAdd(&g_cnt[cb], 0) < NSPLITS) __nanosleep(100);
        __threadfence();                    // acquire partials
        g_cnt[cb] = 0;                      // reset for next graph replay
    }
    __syncthreads();

    if (tid < NSPLITS) {
        c_m[tid] = g_m[cb * NSPLITS + tid];
        c_l[tid] = g_l[cb * NSPLITS + tid];
    }
    __syncthreads();

    float mg = -CUDART_INF_F;
    #pragma unroll
    for (int i = 0; i < NSPLITS; i++) mg = fmaxf(mg, c_m[i]);
    if (tid < NSPLITS)
        c_w[tid] = (c_l[tid] > 0.0f) ? __expf(c_m[tid] - mg) : 0.0f;
    __syncthreads();

    float ltot = 0.0f;
    #pragma unroll
    for (int i = 0; i < NSPLITS; i++) ltot = fmaf(c_l[i], c_w[i], ltot);
    const float inv = 1.0f / ltot;

    float4 rr = make_float4(0.f, 0.f, 0.f, 0.f);
    const float4* accp = reinterpret_cast<const float4*>(g_acc) +
                         (size_t)cb * NSPLITS * (D_DIM / 4) + tid;
    #pragma unroll 8
    for (int i = 0; i < NSPLITS; i++) {
        const float4 a = accp[i * (D_DIM / 4)];
        const float wi = c_w[i];
        rr.x = fmaf(a.x, wi, rr.x);
        rr.y = fmaf(a.y, wi, rr.y);
        rr.z = fmaf(a.z, wi, rr.z);
        rr.w = fmaf(a.w, wi, rr.w);
    }
    rr.x *= inv; rr.y *= inv; rr.z *= inv; rr.w *= inv;
    reinterpret_cast<float4*>(out + (size_t)cb * D_DIM)[tid] = rr;
}

// ---------------------------------------------------------------------------
// Launch.  Inputs bound by element count:
//   B*S   = 131072    -> enc_mask (int32; JAX bool materialized as int32)
//   B*S*D = 134217728 -> enc_out  (f32)
//   B*D   = 65536     -> dec_hid  (f32)
// ---------------------------------------------------------------------------
extern "C" void kernel_launch(void* const* d_in, const int* in_sizes, int n_in,
                              void* d_out, int out_size)
{
    const int*   enc_mask = nullptr;
    const float* enc_out  = nullptr;
    const float* dec_hid  = nullptr;

    for (int i = 0; i < n_in; i++) {
        if (in_sizes[i] == B_DIM * S_DIM)            enc_mask = (const int*)d_in[i];
        else if (in_sizes[i] == B_DIM * D_DIM)       dec_hid  = (const float*)d_in[i];
        else                                          enc_out  = (const float*)d_in[i];
    }

    cudaFuncSetAttribute(luong_fused_kernel,
                         cudaFuncAttributeMaxDynamicSharedMemorySize,
                         DYN_SMEM_BYTES);

    luong_fused_kernel<<<GRID1, THREADS, DYN_SMEM_BYTES>>>(
        enc_mask, enc_out, dec_hid, (float*)d_out);
}